// round 15
// baseline (speedup 1.0000x reference)
#include <cuda_runtime.h>

// Problem constants
#define B_  8192
#define T_  336
#define F_  8
#define H_  20
#define L_  3
#define ITER (T_ + 2 * (L_ - 1)) // 340

typedef unsigned long long u64;

// ---- packed f32x2 helpers (sm_103a) ----
__device__ __forceinline__ u64 pk(float lo, float hi) {
    u64 r; asm("mov.b64 %0, {%1, %2};" : "=l"(r) : "f"(lo), "f"(hi)); return r;
}
__device__ __forceinline__ float2 upk(u64 v) {
    float2 f; asm("mov.b64 {%0, %1}, %2;" : "=f"(f.x), "=f"(f.y) : "l"(v)); return f;
}
__device__ __forceinline__ u64 ffma2(u64 a, u64 b, u64 c) {
    u64 d; asm("fma.rn.f32x2 %0, %1, %2, %3;" : "=l"(d) : "l"(a), "l"(b), "l"(c)); return d;
}
__device__ __forceinline__ u64 fmul2(u64 a, u64 b) {
    u64 d; asm("mul.rn.f32x2 %0, %1, %2;" : "=l"(d) : "l"(a), "l"(b)); return d;
}
__device__ __forceinline__ float tanhap(float x) {   // MUFU.TANH
    float y; asm("tanh.approx.f32 %0, %1;" : "=f"(y) : "f"(x)); return y;
}

// ============================================================================
// Fused 3-layer LSTM + FC head. Block = 4 elements (2 packed pairs),
// 128 threads (120 work + 8 mirrors). Weight registers amortized over 2 pairs.
// Thread (l, r): r = u*2 + half; half0 owns rows {u,u+40} (i,g), half1 owns
// {u+20,u+60} (f,o). BALANCED cell update: half0 updates pair0 (recv f0,o0),
// half1 updates pair1 (recv i1*g1) -- 2 shfl_xor(1) with per-half payloads.
// L0 gmem staging via 8 threads x float4. All activations MUFU.TANH.
// Single barrier per iter; wavefront skew 2 (layer l at iter j: t = j - 2l).
// ============================================================================
__global__ __launch_bounds__(128, 3)
void lstm_fused3(
    const float* __restrict__ x,
    const float* __restrict__ W_ih0, const float* __restrict__ W_hh0,
    const float* __restrict__ b_ih0, const float* __restrict__ b_hh0,
    const float* __restrict__ W_ih1, const float* __restrict__ W_hh1,
    const float* __restrict__ b_ih1, const float* __restrict__ b_hh1,
    const float* __restrict__ W_ih2, const float* __restrict__ W_hh2,
    const float* __restrict__ b_ih2, const float* __restrict__ b_hh2,
    const float* __restrict__ fc1_w, const float* __restrict__ fc1_b,
    const float* __restrict__ fc2_w, const float* __restrict__ fc2_b,
    float* __restrict__ out_final)
{
    // h ring: [layer][slot][elem0..3][unit]
    __shared__ __align__(16) float s_h[L_][4][4][H_];
    // L0 input ring, padded to 20 feats (8..19 stay zero)
    __shared__ __align__(16) float s_x0[4][4][H_];
    __shared__ float s_fc[4][H_];

    const int tid  = threadIdx.x;
    int l = tid / 40; if (l > 2) l = 2;          // tids 120..127 mirror layer 2
    const int r    = (tid - l * 40) % 40;        // 0..39
    const int u    = r >> 1;
    const int half = r & 1;
    const size_t blk = blockIdx.x;               // 4 elems: 4*blk .. 4*blk+3

    const int row0 = u + 20 * half;              // i or f
    const int row1 = u + 40 + 20 * half;         // g or o

    const float* __restrict__ Wih = (l == 0) ? W_ih0 : (l == 1) ? W_ih1 : W_ih2;
    const float* __restrict__ Whh = (l == 0) ? W_hh0 : (l == 1) ? W_hh1 : W_hh2;
    const float* __restrict__ bih = (l == 0) ? b_ih0 : (l == 1) ? b_ih1 : b_ih2;
    const float* __restrict__ bhh = (l == 0) ? b_hh0 : (l == 1) ? b_hh1 : b_hh2;
    const int INl = (l == 0) ? F_ : H_;

    // k-packed weights: w[q] = {W[row][2q], W[row][2q+1]}; W_ih zero-padded to 20
    u64 whhA[H_ / 2], whhB[H_ / 2], wihA[H_ / 2], wihB[H_ / 2];
    #pragma unroll
    for (int q = 0; q < H_ / 2; ++q) {
        whhA[q] = pk(__ldg(&Whh[row0 * H_ + 2 * q]), __ldg(&Whh[row0 * H_ + 2 * q + 1]));
        whhB[q] = pk(__ldg(&Whh[row1 * H_ + 2 * q]), __ldg(&Whh[row1 * H_ + 2 * q + 1]));
        float a0 = (2 * q     < INl) ? __ldg(&Wih[row0 * INl + 2 * q])     : 0.f;
        float a1 = (2 * q + 1 < INl) ? __ldg(&Wih[row0 * INl + 2 * q + 1]) : 0.f;
        float b0 = (2 * q     < INl) ? __ldg(&Wih[row1 * INl + 2 * q])     : 0.f;
        float b1 = (2 * q + 1 < INl) ? __ldg(&Wih[row1 * INl + 2 * q + 1]) : 0.f;
        wihA[q] = pk(a0, a1);
        wihB[q] = pk(b0, b1);
    }
    const float bias0 = __ldg(&bih[row0]) + __ldg(&bhh[row0]);
    const float bias1 = __ldg(&bih[row1]) + __ldg(&bhh[row1]);
    // row0 always sigmoid (= .5*tanh(.5x)+.5); row1 tanh (half0) / sigmoid (half1)
    const float ks1 = half ? 0.5f : 1.f;
    const u64 am2 = half ? pk(0.5f, 0.5f) : pk(1.f, 1.f);
    const u64 bm2 = half ? pk(0.5f, 0.5f) : pk(0.f, 0.f);
    const u64 h2c = pk(0.5f, 0.5f);

    // L0 staging role: l==0 && r<8 -> (selem = r&3, hi = r>>2), float4 each
    const int selem = r & 3, hi = (r >> 2) & 1;
    const float4* __restrict__ myin4 =
        (const float4*)(x + (size_t)(4 * blk + selem) * T_ * F_) + hi;

    // ---- zero-init smem rings ----
    for (int i = tid; i < L_ * 4 * 4 * H_; i += 128) ((float*)s_h)[i] = 0.f;
    for (int i = tid; i < 4 * 4 * H_; i += 128)      ((float*)s_x0)[i] = 0.f;
    __syncthreads();

    // stage x[0], x[1]; prefetch x[2]   (each t = 2 float4 per elem)
    float4 xr4 = make_float4(0.f, 0.f, 0.f, 0.f);
    float4* const s_x0q = (float4*)s_x0;   // [slot*4+selem] has 5 float4; use first 2
    if (l == 0 && r < 8) {
        s_x0q[(0 * 4 + selem) * 5 + hi] = myin4[0];
        s_x0q[(1 * 4 + selem) * 5 + hi] = myin4[2];
        xr4 = myin4[4];
    }
    __syncthreads();

    // K-packed dot over a [2][20]-float vector: 4 independent 10-FFMA2 chains
    #define KDOT(vbase, wA, wB, o00, o01, o10, o11) do {                       \
        const ulonglong2* _v0 = (const ulonglong2*)(vbase);                    \
        const ulonglong2* _v1 = (const ulonglong2*)((vbase) + H_);             \
        u64 _a00 = 0ULL, _a01 = 0ULL, _a10 = 0ULL, _a11 = 0ULL;                \
        _Pragma("unroll")                                                      \
        for (int q = 0; q < 5; ++q) {                                          \
            ulonglong2 _p0 = _v0[q], _p1 = _v1[q];                             \
            _a00 = ffma2(_p0.x, wA[2 * q],     _a00);                          \
            _a00 = ffma2(_p0.y, wA[2 * q + 1], _a00);                          \
            _a01 = ffma2(_p1.x, wA[2 * q],     _a01);                          \
            _a01 = ffma2(_p1.y, wA[2 * q + 1], _a01);                          \
            _a10 = ffma2(_p0.x, wB[2 * q],     _a10);                          \
            _a10 = ffma2(_p0.y, wB[2 * q + 1], _a10);                          \
            _a11 = ffma2(_p1.x, wB[2 * q],     _a11);                          \
            _a11 = ffma2(_p1.y, wB[2 * q + 1], _a11);                          \
        }                                                                      \
        float2 _f;                                                             \
        _f = upk(_a00); o00 = _f.x + _f.y;                                     \
        _f = upk(_a01); o01 = _f.x + _f.y;                                     \
        _f = upk(_a10); o10 = _f.x + _f.y;                                     \
        _f = upk(_a11); o11 = _f.x + _f.y;                                     \
    } while (0)

    // carried x-part per pair: [pair][rowA e0, rowA e1, rowB e0, rowB e1]
    float xp[2][4];
    #pragma unroll
    for (int P = 0; P < 2; ++P) {
        const float* vb = (l == 0) ? &s_x0[0][2 * P][0] : &s_h[l - 1][2][2 * P][0];
        KDOT(vb, wihA, wihB, xp[P][0], xp[P][1], xp[P][2], xp[P][3]);
        xp[P][0] += bias0; xp[P][1] += bias0; xp[P][2] += bias1; xp[P][3] += bias1;
    }

    u64 c2 = 0ULL;   // cell state for MY pair (half0 -> pair0, half1 -> pair1)

    for (int j = 0; j < ITER; ++j) {
        const int tl = j - 2 * l;
        const bool active = (tl >= 0) && (tl < T_);

        // stage x[j+2] (float4); prefetch x[j+3]
        if (l == 0 && r < 8) {
            if (j + 2 < T_) s_x0q[(((j + 2) & 3) * 4 + selem) * 5 + hi] = xr4;
            const int tn = (j + 3 < T_) ? j + 3 : T_ - 1;
            xr4 = myin4[(size_t)tn * 2];
        }

        // critical: W_hh · h[t-1] for both pairs (ring slot (j+3)&3 == (j-1)&3)
        float pre[2][4];
        #pragma unroll
        for (int P = 0; P < 2; ++P) {
            float s0, s1, s2, s3;
            KDOT(&s_h[l][(j + 3) & 3][2 * P][0], whhA, whhB, s0, s1, s2, s3);
            pre[P][0] = xp[P][0] + s0; pre[P][1] = xp[P][1] + s1;
            pre[P][2] = xp[P][2] + s2; pre[P][3] = xp[P][3] + s3;
        }

        // activations — all MUFU.TANH, packed epilogues
        u64 Y0[2], Y1[2];
        #pragma unroll
        for (int P = 0; P < 2; ++P) {
            Y0[P] = ffma2(pk(tanhap(0.5f * pre[P][0]), tanhap(0.5f * pre[P][1])), h2c, h2c);
            Y1[P] = ffma2(pk(tanhap(ks1 * pre[P][2]),  tanhap(ks1 * pre[P][3])),  am2, bm2);
        }
        const u64 Pp0 = fmul2(Y0[0], Y1[0]);   // half0: i0*g0 (used); half1: f0*o0
        const u64 Pp1 = fmul2(Y0[1], Y1[1]);   // half0: i1*g1 (shipped); half1: f1*o1

        // balanced exchange: half0 <- {f0, o0}; half1 <- {i1*g1}
        const u64 sendA = half ? Y0[0] : Pp1;
        const u64 recvA = __shfl_xor_sync(0xFFFFFFFFu, sendA, 1);
        const u64 recvB = __shfl_xor_sync(0xFFFFFFFFu, Y1[0], 1);

        if (active) {   // each half updates its OWN pair
            const u64 fg = half ? Y0[1] : recvA;    // forget gate of my pair
            const u64 ig = half ? recvA : Pp0;      // i*g of my pair
            const u64 og = half ? Y1[1] : recvB;    // output gate of my pair
            c2 = ffma2(fg, c2, ig);
            float2 cf = upk(c2);
            float2 hf = upk(fmul2(og, pk(tanhap(cf.x), tanhap(cf.y))));
            s_h[l][j & 3][2 * half][u]     = hf.x;
            s_h[l][j & 3][2 * half + 1][u] = hf.y;
        }

        // bubble: x-part for iter j+1 (inputs synced at previous barrier)
        #pragma unroll
        for (int P = 0; P < 2; ++P) {
            const float* vb = (l == 0)
                ? &s_x0[(j + 1) & 3][2 * P][0]
                : &s_h[l - 1][(j + 3) & 3][2 * P][0];
            float s0, s1, s2, s3;
            KDOT(vb, wihA, wihB, s0, s1, s2, s3);
            xp[P][0] = bias0 + s0; xp[P][1] = bias0 + s1;
            xp[P][2] = bias1 + s2; xp[P][3] = bias1 + s3;
        }

        __syncthreads();
    }

    // ---- FC head on layer 2's final h (ring slot (ITER-1)&3 = 3) ----
    if (l == 2) {   // thread (u, half) -> elems {2*half, 2*half+1}, unit u
        #pragma unroll
        for (int em2 = 0; em2 < 2; ++em2) {
            const int em = 2 * half + em2;
            const float* hfin = &s_h[2][(ITER - 1) & 3][em][0];
            float d = __ldg(&fc1_b[u]);
            #pragma unroll
            for (int k = 0; k < H_; ++k)
                d = fmaf(hfin[k], __ldg(&fc1_w[u * H_ + k]), d);
            d = fmaxf(d, 0.f);
            s_fc[em][u] = d * __ldg(&fc2_w[u]);
        }
    }
    __syncthreads();
    if (tid >= 80 && tid < 84) {   // layer-2 r = 0..3: one output elem each
        const int po = tid - 80;
        float p = __ldg(&fc2_b[0]);
        #pragma unroll
        for (int k = 0; k < H_; ++k) p += s_fc[po][k];
        out_final[4 * blk + po] = p;
    }
}

extern "C" void kernel_launch(void* const* d_in, const int* in_sizes, int n_in,
                              void* d_out, int out_size) {
    const float* x     = (const float*)d_in[0];
    const float* Wih0  = (const float*)d_in[1];
    const float* Whh0  = (const float*)d_in[2];
    const float* bih0  = (const float*)d_in[3];
    const float* bhh0  = (const float*)d_in[4];
    const float* Wih1  = (const float*)d_in[5];
    const float* Whh1  = (const float*)d_in[6];
    const float* bih1  = (const float*)d_in[7];
    const float* bhh1  = (const float*)d_in[8];
    const float* Wih2  = (const float*)d_in[9];
    const float* Whh2  = (const float*)d_in[10];
    const float* bih2  = (const float*)d_in[11];
    const float* bhh2  = (const float*)d_in[12];
    const float* fc1w  = (const float*)d_in[13];
    const float* fc1b  = (const float*)d_in[14];
    const float* fc2w  = (const float*)d_in[15];
    const float* fc2b  = (const float*)d_in[16];
    float* out = (float*)d_out;

    lstm_fused3<<<B_ / 4, 128>>>(
        x,
        Wih0, Whh0, bih0, bhh0,
        Wih1, Whh1, bih1, bhh1,
        Wih2, Whh2, bih2, bhh2,
        fc1w, fc1b, fc2w, fc2b,
        out);
}

// round 16
// speedup vs baseline: 1.0343x; 1.0343x over previous
#include <cuda_runtime.h>

// Problem constants
#define B_  8192
#define T_  336
#define F_  8
#define H_  20
#define L_  3
#define NP_ 4                    // pairs per block (8 elements)
#define NE_ (2 * NP_)            // 8 elements per block
#define ITER (T_ + 2 * (L_ - 1)) // 340

typedef unsigned long long u64;

// ---- packed f32x2 helpers (sm_103a) ----
__device__ __forceinline__ u64 pk(float lo, float hi) {
    u64 r; asm("mov.b64 %0, {%1, %2};" : "=l"(r) : "f"(lo), "f"(hi)); return r;
}
__device__ __forceinline__ float2 upk(u64 v) {
    float2 f; asm("mov.b64 {%0, %1}, %2;" : "=f"(f.x), "=f"(f.y) : "l"(v)); return f;
}
__device__ __forceinline__ u64 ffma2(u64 a, u64 b, u64 c) {
    u64 d; asm("fma.rn.f32x2 %0, %1, %2, %3;" : "=l"(d) : "l"(a), "l"(b), "l"(c)); return d;
}
__device__ __forceinline__ u64 fmul2(u64 a, u64 b) {
    u64 d; asm("mul.rn.f32x2 %0, %1, %2;" : "=l"(d) : "l"(a), "l"(b)); return d;
}
__device__ __forceinline__ float tanhap(float x) {   // MUFU.TANH
    float y; asm("tanh.approx.f32 %0, %1;" : "=f"(y) : "f"(x)); return y;
}

// ============================================================================
// Fused 3-layer LSTM + FC head. Block = 8 elements (4 packed pairs),
// 128 threads (120 work + 8 mirrors). Weight registers amortized over 4 pairs.
// Thread (l, r): r = u*2 + half; half0 owns rows {u,u+40} (i,g), half1 owns
// {u+20,u+60} (f,o); i*g ships to half1 via one 64-bit shfl_xor(1) per pair;
// half1 does all cell updates (lane "balance" is predication-only — R15).
// All activations MUFU.TANH. Single barrier per iter.
// Wavefront skew 2: layer l at iter j computes t = j - 2l.
// ============================================================================
__global__ __launch_bounds__(128, 3)
void lstm_fused3(
    const float* __restrict__ x,
    const float* __restrict__ W_ih0, const float* __restrict__ W_hh0,
    const float* __restrict__ b_ih0, const float* __restrict__ b_hh0,
    const float* __restrict__ W_ih1, const float* __restrict__ W_hh1,
    const float* __restrict__ b_ih1, const float* __restrict__ b_hh1,
    const float* __restrict__ W_ih2, const float* __restrict__ W_hh2,
    const float* __restrict__ b_ih2, const float* __restrict__ b_hh2,
    const float* __restrict__ fc1_w, const float* __restrict__ fc1_b,
    const float* __restrict__ fc2_w, const float* __restrict__ fc2_b,
    float* __restrict__ out_final)
{
    // h ring: [layer][slot][elem0..7][unit]
    __shared__ __align__(16) float s_h[L_][4][NE_][H_];
    // L0 input ring, padded to 20 feats (8..19 stay zero)
    __shared__ __align__(16) float s_x0[4][NE_][H_];
    __shared__ float s_fc[NE_][H_];

    const int tid  = threadIdx.x;
    int l = tid / 40; if (l > 2) l = 2;          // tids 120..127 mirror layer 2
    const int r    = (tid - l * 40) % 40;        // 0..39
    const int u    = r >> 1;
    const int half = r & 1;
    const size_t blk = blockIdx.x;               // elems: NE_*blk .. NE_*blk+7

    const int row0 = u + 20 * half;              // i or f
    const int row1 = u + 40 + 20 * half;         // g or o

    const float* __restrict__ Wih = (l == 0) ? W_ih0 : (l == 1) ? W_ih1 : W_ih2;
    const float* __restrict__ Whh = (l == 0) ? W_hh0 : (l == 1) ? W_hh1 : W_hh2;
    const float* __restrict__ bih = (l == 0) ? b_ih0 : (l == 1) ? b_ih1 : b_ih2;
    const float* __restrict__ bhh = (l == 0) ? b_hh0 : (l == 1) ? b_hh1 : b_hh2;
    const int INl = (l == 0) ? F_ : H_;

    // k-packed weights: w[q] = {W[row][2q], W[row][2q+1]}; W_ih zero-padded to 20
    u64 whhA[H_ / 2], whhB[H_ / 2], wihA[H_ / 2], wihB[H_ / 2];
    #pragma unroll
    for (int q = 0; q < H_ / 2; ++q) {
        whhA[q] = pk(__ldg(&Whh[row0 * H_ + 2 * q]), __ldg(&Whh[row0 * H_ + 2 * q + 1]));
        whhB[q] = pk(__ldg(&Whh[row1 * H_ + 2 * q]), __ldg(&Whh[row1 * H_ + 2 * q + 1]));
        float a0 = (2 * q     < INl) ? __ldg(&Wih[row0 * INl + 2 * q])     : 0.f;
        float a1 = (2 * q + 1 < INl) ? __ldg(&Wih[row0 * INl + 2 * q + 1]) : 0.f;
        float b0 = (2 * q     < INl) ? __ldg(&Wih[row1 * INl + 2 * q])     : 0.f;
        float b1 = (2 * q + 1 < INl) ? __ldg(&Wih[row1 * INl + 2 * q + 1]) : 0.f;
        wihA[q] = pk(a0, a1);
        wihB[q] = pk(b0, b1);
    }
    const float bias0 = __ldg(&bih[row0]) + __ldg(&bhh[row0]);
    const float bias1 = __ldg(&bih[row1]) + __ldg(&bhh[row1]);
    // row0 always sigmoid (= .5*tanh(.5x)+.5); row1 tanh (half0) / sigmoid (half1)
    const float ks1 = half ? 0.5f : 1.f;
    const u64 am2 = half ? pk(0.5f, 0.5f) : pk(1.f, 1.f);
    const u64 bm2 = half ? pk(0.5f, 0.5f) : pk(0.f, 0.f);
    const u64 h2c = pk(0.5f, 0.5f);

    // L0 staging role: l==0 && r<16 -> (selem = r>>1, hi = r&1), float4 each
    const int selem = (r >> 1) & 7, hi = r & 1;
    const float4* __restrict__ myin4 =
        (const float4*)(x + (size_t)(NE_ * blk + selem) * T_ * F_) + hi;

    // ---- zero-init smem rings ----
    for (int i = tid; i < L_ * 4 * NE_ * H_; i += 128) ((float*)s_h)[i] = 0.f;
    for (int i = tid; i < 4 * NE_ * H_; i += 128)      ((float*)s_x0)[i] = 0.f;
    __syncthreads();

    // stage x[0], x[1]; prefetch x[2]   (each t = 2 float4 per elem)
    float4 xr4 = make_float4(0.f, 0.f, 0.f, 0.f);
    float4* const s_x0q = (float4*)s_x0;   // [(slot*NE_+selem)*5 + hi]
    if (l == 0 && r < 16) {
        s_x0q[(0 * NE_ + selem) * 5 + hi] = myin4[0];
        s_x0q[(1 * NE_ + selem) * 5 + hi] = myin4[2];
        xr4 = myin4[4];
    }
    __syncthreads();

    // K-packed dot over a [2][20]-float vector: 4 independent 10-FFMA2 chains
    #define KDOT(vbase, wA, wB, o00, o01, o10, o11) do {                       \
        const ulonglong2* _v0 = (const ulonglong2*)(vbase);                    \
        const ulonglong2* _v1 = (const ulonglong2*)((vbase) + H_);             \
        u64 _a00 = 0ULL, _a01 = 0ULL, _a10 = 0ULL, _a11 = 0ULL;                \
        _Pragma("unroll")                                                      \
        for (int q = 0; q < 5; ++q) {                                          \
            ulonglong2 _p0 = _v0[q], _p1 = _v1[q];                             \
            _a00 = ffma2(_p0.x, wA[2 * q],     _a00);                          \
            _a00 = ffma2(_p0.y, wA[2 * q + 1], _a00);                          \
            _a01 = ffma2(_p1.x, wA[2 * q],     _a01);                          \
            _a01 = ffma2(_p1.y, wA[2 * q + 1], _a01);                          \
            _a10 = ffma2(_p0.x, wB[2 * q],     _a10);                          \
            _a10 = ffma2(_p0.y, wB[2 * q + 1], _a10);                          \
            _a11 = ffma2(_p1.x, wB[2 * q],     _a11);                          \
            _a11 = ffma2(_p1.y, wB[2 * q + 1], _a11);                          \
        }                                                                      \
        float2 _f;                                                             \
        _f = upk(_a00); o00 = _f.x + _f.y;                                     \
        _f = upk(_a01); o01 = _f.x + _f.y;                                     \
        _f = upk(_a10); o10 = _f.x + _f.y;                                     \
        _f = upk(_a11); o11 = _f.x + _f.y;                                     \
    } while (0)

    // carried x-part per pair: [pair][rowA e0, rowA e1, rowB e0, rowB e1]
    float xp[NP_][4];
    #pragma unroll
    for (int P = 0; P < NP_; ++P) {
        const float* vb = (l == 0) ? &s_x0[0][2 * P][0] : &s_h[l - 1][2][2 * P][0];
        KDOT(vb, wihA, wihB, xp[P][0], xp[P][1], xp[P][2], xp[P][3]);
        xp[P][0] += bias0; xp[P][1] += bias0; xp[P][2] += bias1; xp[P][3] += bias1;
    }

    u64 c2[NP_];
    #pragma unroll
    for (int P = 0; P < NP_; ++P) c2[P] = 0ULL;

    for (int j = 0; j < ITER; ++j) {
        const int tl = j - 2 * l;
        const bool active = (tl >= 0) && (tl < T_);

        // stage x[j+2] (float4); prefetch x[j+3]
        if (l == 0 && r < 16) {
            if (j + 2 < T_) s_x0q[(((j + 2) & 3) * NE_ + selem) * 5 + hi] = xr4;
            const int tn = (j + 3 < T_) ? j + 3 : T_ - 1;
            xr4 = myin4[(size_t)tn * 2];
        }

        // critical: W_hh · h[t-1] for all pairs (ring slot (j+3)&3 == (j-1)&3)
        // activations — all MUFU.TANH, packed epilogues
        u64 Y0[NP_], Y1[NP_], Pp[NP_], Pr[NP_];
        #pragma unroll
        for (int P = 0; P < NP_; ++P) {
            float s0, s1, s2, s3;
            KDOT(&s_h[l][(j + 3) & 3][2 * P][0], whhA, whhB, s0, s1, s2, s3);
            const float p0 = xp[P][0] + s0, p1 = xp[P][1] + s1;
            const float p2 = xp[P][2] + s2, p3 = xp[P][3] + s3;
            Y0[P] = ffma2(pk(tanhap(0.5f * p0), tanhap(0.5f * p1)), h2c, h2c);
            Y1[P] = ffma2(pk(tanhap(ks1 * p2),  tanhap(ks1 * p3)),  am2, bm2);
            Pp[P] = fmul2(Y0[P], Y1[P]);
        }
        #pragma unroll
        for (int P = 0; P < NP_; ++P)
            Pr[P] = __shfl_xor_sync(0xFFFFFFFFu, Pp[P], 1);

        if (active && half) {   // half1 holds f (Y0) and o (Y1); recv i*g
            #pragma unroll
            for (int P = 0; P < NP_; ++P) {
                c2[P] = ffma2(Y0[P], c2[P], Pr[P]);
                float2 cf = upk(c2[P]);
                float2 hf = upk(fmul2(Y1[P], pk(tanhap(cf.x), tanhap(cf.y))));
                s_h[l][j & 3][2 * P][u]     = hf.x;
                s_h[l][j & 3][2 * P + 1][u] = hf.y;
            }
        }

        // bubble: x-part for iter j+1 (inputs synced at previous barrier)
        #pragma unroll
        for (int P = 0; P < NP_; ++P) {
            const float* vb = (l == 0)
                ? &s_x0[(j + 1) & 3][2 * P][0]
                : &s_h[l - 1][(j + 3) & 3][2 * P][0];
            float s0, s1, s2, s3;
            KDOT(vb, wihA, wihB, s0, s1, s2, s3);
            xp[P][0] = bias0 + s0; xp[P][1] = bias0 + s1;
            xp[P][2] = bias1 + s2; xp[P][3] = bias1 + s3;
        }

        __syncthreads();
    }

    // ---- FC head on layer 2's final h (ring slot (ITER-1)&3) ----
    if (l == 2) {   // thread (u, half) -> elems {4*half .. 4*half+3}, unit u
        #pragma unroll
        for (int em2 = 0; em2 < 4; ++em2) {
            const int em = 4 * half + em2;
            const float* hfin = &s_h[2][(ITER - 1) & 3][em][0];
            float d = __ldg(&fc1_b[u]);
            #pragma unroll
            for (int k = 0; k < H_; ++k)
                d = fmaf(hfin[k], __ldg(&fc1_w[u * H_ + k]), d);
            d = fmaxf(d, 0.f);
            s_fc[em][u] = d * __ldg(&fc2_w[u]);
        }
    }
    __syncthreads();
    if (tid >= 80 && tid < 80 + NE_) {   // layer-2 r = 0..7: one output elem each
        const int po = tid - 80;
        float p = __ldg(&fc2_b[0]);
        #pragma unroll
        for (int k = 0; k < H_; ++k) p += s_fc[po][k];
        out_final[NE_ * blk + po] = p;
    }
}

extern "C" void kernel_launch(void* const* d_in, const int* in_sizes, int n_in,
                              void* d_out, int out_size) {
    const float* x     = (const float*)d_in[0];
    const float* Wih0  = (const float*)d_in[1];
    const float* Whh0  = (const float*)d_in[2];
    const float* bih0  = (const float*)d_in[3];
    const float* bhh0  = (const float*)d_in[4];
    const float* Wih1  = (const float*)d_in[5];
    const float* Whh1  = (const float*)d_in[6];
    const float* bih1  = (const float*)d_in[7];
    const float* bhh1  = (const float*)d_in[8];
    const float* Wih2  = (const float*)d_in[9];
    const float* Whh2  = (const float*)d_in[10];
    const float* bih2  = (const float*)d_in[11];
    const float* bhh2  = (const float*)d_in[12];
    const float* fc1w  = (const float*)d_in[13];
    const float* fc1b  = (const float*)d_in[14];
    const float* fc2w  = (const float*)d_in[15];
    const float* fc2b  = (const float*)d_in[16];
    float* out = (float*)d_out;

    lstm_fused3<<<B_ / NE_, 128>>>(
        x,
        Wih0, Whh0, bih0, bhh0,
        Wih1, Whh1, bih1, bhh1,
        Wih2, Whh2, bih2, bhh2,
        fc1w, fc1b, fc2w, fc2b,
        out);
}